// round 6
// baseline (speedup 1.0000x reference)
#include <cuda_runtime.h>
#include <cuda_fp16.h>
#include <cstdint>

// GPTQLinear: out[M,N] = x[M,K] @ dequant(W)[N,K]^T + bias
// M=8192, K=4096, N=4096, GROUPSIZE=64.
// R5 passed at 755us with fp16-dequant-prepass + mma.sync GEMM.
// R6: fuse dequant into the GEMM. Prepass repacks W to true 4-bit in a
// nibble-plane layout (1 shift + 1 lop3 per half2 in the mainloop), B smem
// traffic drops 4x; scales pre-fused to (s, -z*s) fp16 pairs.

#define M_DIM 8192
#define K_DIM 4096
#define N_DIM 4096

__device__ __align__(256) __half  g_xh[(size_t)M_DIM * K_DIM];     // 64 MB
__device__ __align__(256) uint32_t g_w4[(size_t)N_DIM * (K_DIM/8)]; // 8 MB
__device__ __align__(256) __half2 g_sz[(size_t)N_DIM * 64];         // 1 MB

// ---------------------------------------------------------------------------
__device__ __forceinline__ uint32_t smem_u32(const void* p) {
    uint32_t a;
    asm("{ .reg .u64 t; cvta.to.shared.u64 t, %1; cvt.u32.u64 %0, t; }"
        : "=r"(a) : "l"(p));
    return a;
}

#define LDSM4(R, addr)                                                        \
    asm volatile("ldmatrix.sync.aligned.m8n8.x4.shared.b16 {%0,%1,%2,%3}, [%4];" \
                 : "=r"((R)[0]), "=r"((R)[1]), "=r"((R)[2]), "=r"((R)[3])     \
                 : "r"(addr))

#define MMA16816(C, A, B0, B1)                                                \
    asm volatile("mma.sync.aligned.m16n8k16.row.col.f32.f16.f16.f32 "         \
                 "{%0,%1,%2,%3}, {%4,%5,%6,%7}, {%8,%9}, {%0,%1,%2,%3};"      \
                 : "+f"((C)[0]), "+f"((C)[1]), "+f"((C)[2]), "+f"((C)[3])     \
                 : "r"((A)[0]), "r"((A)[1]), "r"((A)[2]), "r"((A)[3]),        \
                   "r"(B0), "r"(B1))

// ---------------------------------------------------------------------------
// Kernel 1: x fp32 -> fp16  (DRAM-bound, already at roofline)
// ---------------------------------------------------------------------------
__global__ void k_convert_x(const float* __restrict__ x) {
    size_t i = ((size_t)blockIdx.x * 256 + threadIdx.x) * 8;
    float4 a = *reinterpret_cast<const float4*>(x + i);
    float4 b = *reinterpret_cast<const float4*>(x + i + 4);
    union { __half2 h[4]; uint4 u; } o;
    o.h[0] = __floats2half2_rn(a.x, a.y);
    o.h[1] = __floats2half2_rn(a.z, a.w);
    o.h[2] = __floats2half2_rn(b.x, b.y);
    o.h[3] = __floats2half2_rn(b.z, b.w);
    *reinterpret_cast<uint4*>(g_xh + i) = o.u;
}

// ---------------------------------------------------------------------------
// Kernel 2: repack W to nibble-plane 4-bit.
// Source: pw int32[N, K/2]; one byte per int32; k even = low nibble.
// Output word (n, kc, t)  [kc = 32k chunk, t = 0..3]:
//   bits[ 0- 3]=q(2t)    [ 4- 7]=q(2t+8)   [ 8-11]=q(2t+16)  [12-15]=q(2t+24)
//   bits[16-19]=q(2t+1)  [20-23]=q(2t+9)   [24-27]=q(2t+17)  [28-31]=q(2t+25)
// so that half2_j = ((w >> 4j) & 0x000F000F) | 0x64006400 = (1024+q_lo, 1024+q_hi)
// for the b-fragment pair of k16-block (j>>1), reg (j&1).
// ---------------------------------------------------------------------------
__global__ void k_pack_w(const int* __restrict__ pw) {
    uint32_t idx = blockIdx.x * 256 + threadIdx.x;       // [0, N*512)
    uint32_t n  = idx >> 9;
    uint32_t w  = idx & 511;                             // kc*4 + t
    uint32_t kc = w >> 2, t = w & 3;
    const int* s = pw + (size_t)n * (K_DIM / 2) + kc * 16 + t;
    uint32_t v0 = (uint32_t)s[0]  & 0xFFu;
    uint32_t v1 = (uint32_t)s[4]  & 0xFFu;
    uint32_t v2 = (uint32_t)s[8]  & 0xFFu;
    uint32_t v3 = (uint32_t)s[12] & 0xFFu;
    uint32_t out = (v0 & 0xF) | ((v1 & 0xF) << 4) | ((v2 & 0xF) << 8)
                 | ((v3 & 0xF) << 12)
                 | ((v0 & 0xF0) << 12) | ((v1 & 0xF0) << 16)
                 | ((v2 & 0xF0) << 20) | ((v3 & 0xF0) << 24);
    g_w4[idx] = out;
}

// ---------------------------------------------------------------------------
// Kernel 3: fuse scales: g_sz[n][g] = half2(s, -z*s)
// ---------------------------------------------------------------------------
__global__ void k_scale(const float* __restrict__ scales,
                        const float* __restrict__ zeros) {
    uint32_t idx = blockIdx.x * 256 + threadIdx.x;       // [0, N*64)
    float s = scales[idx];
    g_sz[idx] = __floats2half2_rn(s, -zeros[idx] * s);
}

// ---------------------------------------------------------------------------
// Kernel 4: GEMM. CTA 128x128, BK=32, 4-stage cp.async, 8 warps of 64x32.
// A: fp16 smem (64B rows, 16B-seg swizzle). B: packed 4-bit smem, register
// dequant. fp32 accumulate.
// ---------------------------------------------------------------------------
#define BM 128
#define BN 128
#define BK 32
#define A_TILE_B   (BM * 64)             // 8 KB per stage
#define B_TILE_B   (BM * 16)             // 2 KB per stage (128 rows x 16B)
#define N_STAGES   4
#define A_TOT      (N_STAGES * A_TILE_B) // 32 KB
#define SMEM_BYTES (A_TOT + N_STAGES * B_TILE_B)  // 40 KB
#define NK (K_DIM / BK)                  // 128

#define LOAD_CHUNK(s, kc) do {                                                 \
    const uint32_t sa_ = sb + (uint32_t)(s) * A_TILE_B;                        \
    const int ko_ = (kc) * BK;                                                 \
    _Pragma("unroll")                                                          \
    for (int i_ = 0; i_ < 2; i_++)                                             \
        asm volatile("cp.async.cg.shared.global [%0], [%1], 16;"               \
                     :: "r"(sa_ + a_dst[i_]), "l"(a_src[i_] + ko_) : "memory");\
    if (tid < BM)                                                              \
        asm volatile("cp.async.cg.shared.global [%0], [%1], 16;"               \
                     :: "r"(sb + A_TOT + (uint32_t)(s) * B_TILE_B + tid * 16), \
                        "l"(b_src + (kc) * 4) : "memory");                     \
    asm volatile("cp.async.commit_group;" ::: "memory");                       \
} while (0)

__global__ void __launch_bounds__(256, 2)
k_gemm(const float* __restrict__ bias, float* __restrict__ out) {
    extern __shared__ char smem[];
    const uint32_t sb = smem_u32(smem);
    const int tid = threadIdx.x;
    const int wid = tid >> 5;
    const int lid = tid & 31;
    const int n0 = (int)(blockIdx.x & 31) * BN;    // N fastest: W stays in L2
    const int m0 = (int)(blockIdx.x >> 5) * BM;

    // ---- cp.async sources ----
    const __half* a_src[2]; uint32_t a_dst[2];
    {
        const __half* ab = g_xh + (size_t)m0 * K_DIM;
        #pragma unroll
        for (int i = 0; i < 2; i++) {
            int q = tid + i * 256;
            int r = q >> 2, seg = q & 3;
            a_dst[i] = (uint32_t)(r * 64 + ((seg ^ ((r >> 1) & 3)) << 4));
            a_src[i] = ab + (size_t)r * K_DIM + seg * 8;
        }
    }
    const uint32_t* b_src = g_w4 + (size_t)(n0 + tid) * (K_DIM / 8);  // tid<128

    // ---- A ldmatrix addresses (relative to stage base) ----
    const int wm = wid & 1;       // 64 M-rows
    const int wn = wid >> 1;      // 32 N-cols
    uint32_t a_off[4][2];
    #pragma unroll
    for (int mt = 0; mt < 4; mt++) {
        int r = wm * 64 + mt * 16 + (lid & 15);
        #pragma unroll
        for (int s16 = 0; s16 < 2; s16++) {
            int seg = s16 * 2 + (lid >> 4);
            a_off[mt][s16] = (uint32_t)(r * 64 + ((seg ^ ((r >> 1) & 3)) << 4));
        }
    }
    // B smem read address (nibble-plane words): row n -> 16B, word t = lid&3
    const uint32_t b_rd = sb + A_TOT
                        + (uint32_t)((wn * 32 + (lid >> 2)) * 16 + (lid & 3) * 4);

    float c[4][4][4];
    #pragma unroll
    for (int mt = 0; mt < 4; mt++)
        #pragma unroll
        for (int nt = 0; nt < 4; nt++)
            #pragma unroll
            for (int j = 0; j < 4; j++) c[mt][nt][j] = 0.0f;

    LOAD_CHUNK(0, 0);
    LOAD_CHUNK(1, 1);
    LOAD_CHUNK(2, 2);

    const __half2 H1024 = __floats2half2_rn(1024.0f, 1024.0f);
    __half2 s2[4], zb2[4];

    for (int kc = 0; kc < NK; ++kc) {
        if (kc < NK - 2)       asm volatile("cp.async.wait_group 2;" ::: "memory");
        else if (kc == NK - 2) asm volatile("cp.async.wait_group 1;" ::: "memory");
        else                   asm volatile("cp.async.wait_group 0;" ::: "memory");
        __syncthreads();

        if (kc + 3 < NK) LOAD_CHUNK((kc + 3) & 3, kc + 3);

        // group scales (GROUPSIZE=64 = 2 chunks)
        if ((kc & 1) == 0) {
            const int g = kc >> 1;
            #pragma unroll
            for (int nt = 0; nt < 4; nt++) {
                __half2 v = g_sz[(size_t)(n0 + wn * 32 + nt * 8 + (lid >> 2)) * 64 + g];
                s2[nt]  = __half2half2(__low2half(v));
                zb2[nt] = __half2half2(__high2half(v));
            }
        }

        // ---- B: load packed word per n-tile, dequant to 4 half2 frags ----
        const uint32_t bst = b_rd + (uint32_t)(kc & 3) * B_TILE_B;
        uint32_t bfr[4][4];
        #pragma unroll
        for (int nt = 0; nt < 4; nt++) {
            uint32_t wv;
            asm volatile("ld.shared.b32 %0, [%1];" : "=r"(wv)
                         : "r"(bst + nt * 128));
            #pragma unroll
            for (int j = 0; j < 4; j++) {
                uint32_t u = ((wv >> (4 * j)) & 0x000F000Fu) | 0x64006400u;
                __half2 q = __hsub2(*reinterpret_cast<__half2*>(&u), H1024);
                __half2 wgt = __hfma2(q, s2[nt], zb2[nt]);
                bfr[nt][j] = *reinterpret_cast<uint32_t*>(&wgt);
            }
        }

        const uint32_t st = sb + (uint32_t)(kc & 3) * A_TILE_B;
        #pragma unroll
        for (int s16 = 0; s16 < 2; s16++) {
            uint32_t a[4][4];
            #pragma unroll
            for (int mt = 0; mt < 4; mt++) LDSM4(a[mt], st + a_off[mt][s16]);
            #pragma unroll
            for (int mt = 0; mt < 4; mt++) {
                #pragma unroll
                for (int nt = 0; nt < 4; nt++)
                    MMA16816(c[mt][nt], a[mt], bfr[nt][2 * s16], bfr[nt][2 * s16 + 1]);
            }
        }
    }

    // ---- epilogue: fragment (m16n8): c0,c1 -> (g2, t2..t2+1), c2,c3 -> g2+8
    const int g2 = lid >> 2;
    const int t2 = (lid & 3) << 1;
    #pragma unroll
    for (int mt = 0; mt < 4; mt++) {
        int m = m0 + wm * 64 + mt * 16 + g2;
        float* r0 = out + (size_t)m * N_DIM       + n0 + wn * 32 + t2;
        float* r1 = out + (size_t)(m + 8) * N_DIM + n0 + wn * 32 + t2;
        #pragma unroll
        for (int nt = 0; nt < 4; nt++) {
            float2 bv = *reinterpret_cast<const float2*>(
                bias + n0 + wn * 32 + nt * 8 + t2);
            float2 v0 = { c[mt][nt][0] + bv.x, c[mt][nt][1] + bv.y };
            float2 v1 = { c[mt][nt][2] + bv.x, c[mt][nt][3] + bv.y };
            *reinterpret_cast<float2*>(r0 + nt * 8) = v0;
            *reinterpret_cast<float2*>(r1 + nt * 8) = v1;
        }
    }
}

// ---------------------------------------------------------------------------
extern "C" void kernel_launch(void* const* d_in, const int* in_sizes, int n_in,
                              void* d_out, int out_size) {
    const float* x      = (const float*)d_in[0];
    const int*   pw     = (const int*)d_in[1];
    const float* scales = (const float*)d_in[2];
    const float* zeros  = (const float*)d_in[3];
    const float* bias   = (const float*)d_in[4];
    float* out = (float*)d_out;

    cudaFuncSetAttribute(k_gemm, cudaFuncAttributeMaxDynamicSharedMemorySize,
                         SMEM_BYTES);

    k_convert_x<<<(int)(((size_t)M_DIM * K_DIM / 8) / 256), 256>>>(x);
    k_pack_w<<<(N_DIM * (K_DIM / 8)) / 256, 256>>>(pw);
    k_scale<<<(N_DIM * 64) / 256, 256>>>(scales, zeros);
    k_gemm<<<(M_DIM / BM) * (N_DIM / BN), 256, SMEM_BYTES>>>(bias, out);
}